// round 10
// baseline (speedup 1.0000x reference)
#include <cuda_runtime.h>
#include <math.h>

#define Bn 64
#define Nn 128
#define Dn 32
#define Gn 127              // N-1
#define Pn (Nn*(Nn-1))      // 16256
#define HFn 16
#define EPSf 1e-5f

// ---------------- scratch (static device globals; no allocation) -------------
__device__ float g_U[Bn*Nn*Dn];      // U'[b][n][c] = x@W1_top + b1
__device__ float g_V[Bn*Nn*Dn];      // V [b][n][c] = x@W1_bot
__device__ float g_sumU[Nn], g_sumU2[Nn], g_sumV[Nn], g_sumV2[Nn];
__device__ float g_C[Nn*Nn];         // C[s][t] = sum_{b,c} U'[b,s,c]*V[b,t,c]
__device__ float g_f[Bn*Nn*HFn];     // pre-LN features of final MLP
__device__ float g_fsum[HFn], g_fsum2[HFn];

__device__ __forceinline__ float leaky(float x) { return x > 0.f ? x : 0.01f * x; }

// ---------------- Kernel A: per-node projections + stats + zeroing -----------
__global__ void kA(const float* __restrict__ inp, const float* __restrict__ W1,
                   const float* __restrict__ b1) {
    const int n = blockIdx.x;
    const int b = threadIdx.x;     // 0..63
    __shared__ __align__(16) float W1t[32*64];   // W1t[c*64 + k] = W1[k*32 + c]
    __shared__ float red[64*4];

    // zero g_C slice + f-stat accumulators (consumed by later kernels)
    g_C[n*128 + b*2]     = 0.f;
    g_C[n*128 + b*2 + 1] = 0.f;
    if (n == 0 && b < HFn) { g_fsum[b] = 0.f; g_fsum2[b] = 0.f; }

    for (int idx = b; idx < 2048; idx += 64) {
        int k = idx & 63, c = idx >> 6;
        W1t[c*64 + k] = W1[k*32 + c];
    }
    __syncthreads();

    float x[32];
    const float4* xp = (const float4*)(inp + ((size_t)b*Nn + n)*Dn);
    #pragma unroll
    for (int q = 0; q < 8; q++) {
        float4 v = xp[q];
        x[4*q+0]=v.x; x[4*q+1]=v.y; x[4*q+2]=v.z; x[4*q+3]=v.w;
    }
    float su=0.f, su2=0.f, sv=0.f, sv2=0.f;
    float* Uo = g_U + ((size_t)b*Nn + n)*Dn;
    float* Vo = g_V + ((size_t)b*Nn + n)*Dn;
    #pragma unroll 4
    for (int c = 0; c < 32; c++) {
        const float4* wr = (const float4*)(W1t + c*64);
        float u = b1[c];
        float v = 0.f;
        #pragma unroll
        for (int j = 0; j < 8; j++) {
            float4 wu = wr[j];
            float4 wv = wr[8 + j];
            u += x[4*j+0]*wu.x + x[4*j+1]*wu.y + x[4*j+2]*wu.z + x[4*j+3]*wu.w;
            v += x[4*j+0]*wv.x + x[4*j+1]*wv.y + x[4*j+2]*wv.z + x[4*j+3]*wv.w;
        }
        Uo[c] = u; Vo[c] = v;
        su += u; su2 += u*u; sv += v; sv2 += v*v;
    }
    red[b] = su; red[64+b] = su2; red[128+b] = sv; red[192+b] = sv2;
    __syncthreads();
    for (int s = 32; s > 0; s >>= 1) {
        if (b < s) {
            red[b]     += red[b+s];
            red[64+b]  += red[64+b+s];
            red[128+b] += red[128+b+s];
            red[192+b] += red[192+b+s];
        }
        __syncthreads();
    }
    if (b == 0) {
        g_sumU[n]  = red[0];
        g_sumU2[n] = red[64];
        g_sumV[n]  = red[128];
        g_sumV2[n] = red[192];
    }
}

// ---------------- Kernel B: cross term C[s,t], K-split x8 --------------------
__global__ void kB() {
    const int t0 = blockIdx.x * 16;
    const int s0 = blockIdx.y * 16;
    const int bz = blockIdx.z * 8;
    const int tx = threadIdx.x & 15;
    const int ty = threadIdx.x >> 4;
    __shared__ __align__(16) float Us[16][36];
    __shared__ __align__(16) float Vs[16][36];
    float acc = 0.f;
    for (int b = bz; b < bz + 8; b++) {
        __syncthreads();
        {
            int idx = threadIdx.x;
            int r = idx >> 5, c = idx & 31;
            Us[r][c] = g_U[((size_t)b*Nn + s0 + r)*Dn + c];
            Vs[r][c] = g_V[((size_t)b*Nn + t0 + r)*Dn + c];
            idx += 256; r = idx >> 5; c = idx & 31;
            Us[r][c] = g_U[((size_t)b*Nn + s0 + r)*Dn + c];
            Vs[r][c] = g_V[((size_t)b*Nn + t0 + r)*Dn + c];
        }
        __syncthreads();
        #pragma unroll
        for (int q = 0; q < 8; q++) {
            float4 u = *(const float4*)&Us[ty][4*q];
            float4 v = *(const float4*)&Vs[tx][4*q];
            acc += u.x*v.x + u.y*v.y + u.z*v.z + u.w*v.w;
        }
    }
    atomicAdd(&g_C[(s0+ty)*Nn + (t0+tx)], acc);
}

// ---------------- Kernel C: fused per-edge MLP, 1 batch-edge per thread ------
// grid = (N, B/2), block = 256, dynamic smem, 3 CTAs/SM (85 regs for ILP).
struct SC {
    float W2s[1024];        // W2[k][c] original layout
    float W3s[1056];        // W3[c][33] original layout
    float w3c0[32];         // W3[c][0]
    float b2s[32];
    float b3s[36];
    float us[2][32];
    float xs[2][32];
    float zpart[2][33][4];  // stage-1 partials
    float zs[2][33];        // z[b][c]; c=32 holds gate sum G
    float aggs[2][32];      // agg[b][d]
    union {
        float4 Vt[2][8][128];    // staged V (32 KB)
        float  red[2][33*Gn];    // gate*a2 + gate channel (33.5 KB)
    } u;
};

__global__ void __launch_bounds__(256, 3) kC(
        const float* __restrict__ inp,
        const float* __restrict__ W2, const float* __restrict__ b2,
        const float* __restrict__ W3, const float* __restrict__ b3,
        const float* __restrict__ Wf1, const float* __restrict__ bf1,
        const float* __restrict__ g1, const float* __restrict__ be1,
        float* __restrict__ outEdges) {
    extern __shared__ __align__(16) char smem_raw[];
    SC* S = (SC*)smem_raw;

    const int i  = blockIdx.x;
    const int bb = blockIdx.y * 2;
    const int e  = threadIdx.x;      // 0..255

    // ---- init loads ----
    for (int idx = e; idx < 1024; idx += 256) S->W2s[idx] = W2[idx];
    for (int idx = e; idx < 1056; idx += 256) S->W3s[idx] = W3[idx];
    if (e < 32) { S->w3c0[e] = W3[e*33]; S->b2s[e] = b2[e]; }
    if (e < 33) S->b3s[e] = b3[e];
    if (e < 64) {
        const int b = e >> 5, k = e & 31;
        S->us[b][k] = g_U[((size_t)(bb+b)*Nn + i)*Dn + k];
        S->xs[b][k] = inp[((size_t)(bb+b)*Nn + i)*Dn + k];
    }
    // ---- stage V tile (2 batches x 128 rows x 32 floats), coalesced ----
    {
        const float4* gsrc = (const float4*)(g_V + (size_t)bb*Nn*Dn);
        #pragma unroll
        for (int m = 0; m < 8; m++) {
            int f = m*256 + e;                 // 0..2047 float4s
            int b = f >> 10, rem = f & 1023, tt = rem >> 3, q = rem & 7;
            S->u.Vt[b][q][tt] = gsrc[f];
        }
    }
    __syncthreads();

    const bool active = (e < 2*Gn);            // 254 workers
    const int  b    = active ? (e / Gn) : 0;   // batch within pair
    const int  edge = active ? (e % Gn) : 0;

    float gate = 0.f;
    float acc[32];

    if (active) {
        const int t = edge + (edge >= i);
        const int p = i * Gn + edge;

        // LN scale/shift (depends on p only)
        const float inv = 1.0f / 2048.0f;
        float m  = (g_sumU[i] + g_sumV[t]) * inv;
        float e2 = (g_sumU2[i] + g_sumV2[t] + 2.0f * g_C[i*Nn + t]) * inv;
        float sc = rsqrtf(e2 - m*m + EPSf) * g1[p];
        float sh = be1[p] - m * sc;

        #pragma unroll
        for (int c = 0; c < 32; c++) acc[c] = 0.f;

        const float* ub = S->us[b];
        #pragma unroll
        for (int q = 0; q < 8; q++) {
            float4 v = S->u.Vt[b][q][t];
            float a0 = leaky((ub[4*q+0] + v.x) * sc + sh);
            float a1 = leaky((ub[4*q+1] + v.y) * sc + sh);
            float a2 = leaky((ub[4*q+2] + v.z) * sc + sh);
            float a3 = leaky((ub[4*q+3] + v.w) * sc + sh);

            #pragma unroll
            for (int j = 0; j < 4; j++) {
                const float aj = (j==0) ? a0 : (j==1) ? a1 : (j==2) ? a2 : a3;
                const float4* wrow = (const float4*)(S->W2s + (4*q+j)*32);
                #pragma unroll
                for (int c4 = 0; c4 < 8; c4++) {
                    float4 w = wrow[c4];
                    acc[c4*4+0] += aj*w.x;  acc[c4*4+1] += aj*w.y;
                    acc[c4*4+2] += aj*w.z;  acc[c4*4+3] += aj*w.w;
                }
            }
        }

        // bias + leaky + gate dot (layer-3 column 0)
        float ga = S->b3s[0];
        #pragma unroll
        for (int c = 0; c < 32; c++) {
            acc[c] = leaky(acc[c] + S->b2s[c]);
            ga += acc[c] * S->w3c0[c];
        }
        gate = 1.0f / (1.0f + __expf(-ga));
        outEdges[(size_t)(bb+b)*Pn + p] = gate;
    }

    __syncthreads();   // all Vt reads done -> safe to overwrite union with red

    if (active) {
        #pragma unroll
        for (int c = 0; c < 32; c++)
            S->u.red[b][c*Gn + edge] = gate * acc[c];
        S->u.red[b][32*Gn + edge] = gate;      // gate as channel 32
    }
    __syncthreads();

    // z reduction stage 1: 264 units (b, c, quarter); threads 0..7 take 2 units
    {
        int unit = e;
        #pragma unroll
        for (int pass = 0; pass < 2; pass++) {
            if (unit < 264) {
                const int zb = unit >> 7;           // unit / 132... careful
                // decode: unit = b*132 + c*4 + q  (b:2, c:33, q:4)
                const int bu = unit / 132;
                const int rem = unit - bu*132;
                const int c = rem >> 2;
                const int q = rem & 3;
                const int r0 = q * 32;
                const int r1 = (q == 3) ? Gn : r0 + 32;
                const float* rr = &S->u.red[bu][c*Gn];
                float s = 0.f;
                #pragma unroll 4
                for (int r = r0; r < r1; r++) s += rr[r];
                S->zpart[bu][c][q] = s;
                (void)zb;
            }
            unit += 256;
        }
    }
    __syncthreads();

    // stage 2: 66 threads sum 4 partials
    if (e < 66) {
        const int zb = (e >= 33);
        const int c  = e - zb*33;
        S->zs[zb][c] = (S->zpart[zb][c][0] + S->zpart[zb][c][1])
                     + (S->zpart[zb][c][2] + S->zpart[zb][c][3]);
    }
    __syncthreads();

    // agg[b][d] = G[b]*b3[d+1] + sum_c z[b][c] * W3[c][d+1]
    if (e < 64) {
        const int ab = e >> 5, d = e & 31;
        const float G = S->zs[ab][32];
        float a = G * S->b3s[d+1];
        const float* zb = S->zs[ab];
        #pragma unroll
        for (int c = 0; c < 32; c++) a += zb[c] * S->W3s[c*33 + (d+1)];
        S->aggs[ab][d] = a;
    }
    __syncthreads();

    // f = [x, agg] @ Wf1 + bf1 ; accumulate column stats for the final LN
    if (e < 32) {
        const int fb = e >> 4, c = e & 15;
        float a = bf1[c];
        #pragma unroll
        for (int k = 0; k < 32; k++) a += S->xs[fb][k] * Wf1[k*HFn + c];
        #pragma unroll
        for (int k = 0; k < 32; k++) a += S->aggs[fb][k] * Wf1[(32+k)*HFn + c];
        g_f[((size_t)(bb+fb)*Nn + i)*HFn + c] = a;
        atomicAdd(&g_fsum[c],  a);
        atomicAdd(&g_fsum2[c], a*a);
    }
}

// ---------------- Kernel F: final LN (inline params) + MLP -> out -------------
// grid = 256, block = 128: four threads per row (8 output channels each)
__global__ void kF(const float* __restrict__ gf, const float* __restrict__ bef,
                   const float* __restrict__ Wf2, const float* __restrict__ bf2,
                   float* __restrict__ outp) {
    __shared__ __align__(16) float Wf2s[16*32];
    __shared__ float lnsc[16], lnsh[16], bf2s[32];
    const int tid = threadIdx.x;
    for (int idx = tid; idx < 16*32; idx += 128) Wf2s[idx] = Wf2[idx];
    if (tid < 16) {
        const float invR = 1.0f / 8192.0f;
        float mean = g_fsum[tid] * invR;
        float var  = g_fsum2[tid] * invR - mean * mean;
        float sc = rsqrtf(var + EPSf) * gf[tid];
        lnsc[tid] = sc;
        lnsh[tid] = bef[tid] - mean * sc;
    }
    if (tid < 32) bf2s[tid] = bf2[tid];
    __syncthreads();

    const int gt = blockIdx.x * 128 + tid;   // 0..32767
    const int r = gt >> 2;                   // row 0..8191
    const int part = (gt & 3) * 8;           // output channel base

    float gq[16];
    #pragma unroll
    for (int j = 0; j < 16; j++) {
        float v = g_f[(size_t)r*HFn + j];
        gq[j] = leaky(v * lnsc[j] + lnsh[j]);
    }
    float4* op = (float4*)(outp + (size_t)r * Dn + part);
    #pragma unroll
    for (int q = 0; q < 2; q++) {
        float o[4];
        #pragma unroll
        for (int u = 0; u < 4; u++) {
            int c = part + 4*q + u;
            float a = bf2s[c];
            #pragma unroll
            for (int j = 0; j < 16; j++) a += gq[j] * Wf2s[j*32 + c];
            o[u] = a;
        }
        op[q] = make_float4(o[0], o[1], o[2], o[3]);
    }
}

// ---------------- launch ------------------------------------------------------
extern "C" void kernel_launch(void* const* d_in, const int* in_sizes, int n_in,
                              void* d_out, int out_size) {
    const float* inp = (const float*)d_in[0];
    const float* W1  = (const float*)d_in[3];
    const float* b1  = (const float*)d_in[4];
    const float* g1  = (const float*)d_in[5];
    const float* be1 = (const float*)d_in[6];
    const float* W2  = (const float*)d_in[7];
    const float* b2  = (const float*)d_in[8];
    const float* W3  = (const float*)d_in[9];
    const float* b3  = (const float*)d_in[10];
    const float* Wf1 = (const float*)d_in[11];
    const float* bf1 = (const float*)d_in[12];
    const float* gf  = (const float*)d_in[13];
    const float* bef = (const float*)d_in[14];
    const float* Wf2 = (const float*)d_in[15];
    const float* bf2 = (const float*)d_in[16];

    float* outEdges = (float*)d_out;                       // (B, P)
    float* outFeat  = (float*)d_out + (size_t)Bn * Pn;     // (B, N, D)

    const int smemC = (int)sizeof(SC);
    cudaFuncSetAttribute(kC, cudaFuncAttributeMaxDynamicSharedMemorySize, smemC);

    kA<<<Nn, 64>>>(inp, W1, b1);
    kB<<<dim3(8, 8, 8), 256>>>();
    kC<<<dim3(Nn, Bn/2), 256, smemC>>>(inp, W2, b2, W3, b3, Wf1, bf1, g1, be1, outEdges);
    kF<<<256, 128>>>(gf, bef, Wf2, bf2, outFeat);
}

// round 12
// speedup vs baseline: 1.5765x; 1.5765x over previous
#include <cuda_runtime.h>
#include <math.h>

#define Bn 64
#define Nn 128
#define Dn 32
#define Gn 127              // N-1
#define Pn (Nn*(Nn-1))      // 16256
#define HFn 16
#define EPSf 1e-5f

typedef unsigned int u32;

// ---------------- scratch (static device globals; no allocation) -------------
__device__ float g_U[Bn*Nn*Dn];
__device__ float g_V[Bn*Nn*Dn];
__device__ float g_sumU[Nn], g_sumU2[Nn], g_sumV[Nn], g_sumV2[Nn];
__device__ float g_C[Nn*Nn];
__device__ float g_f[Bn*Nn*HFn];
__device__ float g_fsum[HFn], g_fsum2[HFn];

__device__ __forceinline__ float leaky(float x) { return x > 0.f ? x : 0.01f * x; }

__device__ __forceinline__ u32 tf32b(float x) {
    u32 y; asm("cvt.rna.tf32.f32 %0, %1;" : "=r"(y) : "f"(x));
    return y;
}
__device__ __forceinline__ void mma_tf32(float* d, const u32* a, const u32* b) {
    asm volatile(
        "mma.sync.aligned.m16n8k8.row.col.f32.tf32.tf32.f32 "
        "{%0,%1,%2,%3}, {%4,%5,%6,%7}, {%8,%9}, {%0,%1,%2,%3};"
        : "+f"(d[0]), "+f"(d[1]), "+f"(d[2]), "+f"(d[3])
        : "r"(a[0]), "r"(a[1]), "r"(a[2]), "r"(a[3]), "r"(b[0]), "r"(b[1]));
}

// ---------------- Kernel A: per-node projections + stats + zeroing -----------
__global__ void kA(const float* __restrict__ inp, const float* __restrict__ W1,
                   const float* __restrict__ b1) {
    const int n = blockIdx.x;
    const int b = threadIdx.x;
    __shared__ __align__(16) float W1t[32*64];
    __shared__ float red[64*4];

    g_C[n*128 + b*2]     = 0.f;
    g_C[n*128 + b*2 + 1] = 0.f;
    if (n == 0 && b < HFn) { g_fsum[b] = 0.f; g_fsum2[b] = 0.f; }

    for (int idx = b; idx < 2048; idx += 64) {
        int k = idx & 63, c = idx >> 6;
        W1t[c*64 + k] = W1[k*32 + c];
    }
    __syncthreads();

    float x[32];
    const float4* xp = (const float4*)(inp + ((size_t)b*Nn + n)*Dn);
    #pragma unroll
    for (int q = 0; q < 8; q++) {
        float4 v = xp[q];
        x[4*q+0]=v.x; x[4*q+1]=v.y; x[4*q+2]=v.z; x[4*q+3]=v.w;
    }
    float su=0.f, su2=0.f, sv=0.f, sv2=0.f;
    float* Uo = g_U + ((size_t)b*Nn + n)*Dn;
    float* Vo = g_V + ((size_t)b*Nn + n)*Dn;
    #pragma unroll 4
    for (int c = 0; c < 32; c++) {
        const float4* wr = (const float4*)(W1t + c*64);
        float u = b1[c], v = 0.f;
        #pragma unroll
        for (int j = 0; j < 8; j++) {
            float4 wu = wr[j], wv = wr[8 + j];
            u += x[4*j+0]*wu.x + x[4*j+1]*wu.y + x[4*j+2]*wu.z + x[4*j+3]*wu.w;
            v += x[4*j+0]*wv.x + x[4*j+1]*wv.y + x[4*j+2]*wv.z + x[4*j+3]*wv.w;
        }
        Uo[c] = u; Vo[c] = v;
        su += u; su2 += u*u; sv += v; sv2 += v*v;
    }
    red[b] = su; red[64+b] = su2; red[128+b] = sv; red[192+b] = sv2;
    __syncthreads();
    for (int s = 32; s > 0; s >>= 1) {
        if (b < s) {
            red[b] += red[b+s]; red[64+b] += red[64+b+s];
            red[128+b] += red[128+b+s]; red[192+b] += red[192+b+s];
        }
        __syncthreads();
    }
    if (b == 0) {
        g_sumU[n] = red[0]; g_sumU2[n] = red[64];
        g_sumV[n] = red[128]; g_sumV2[n] = red[192];
    }
}

// ---------------- Kernel B: cross term C[s,t], K-split x8 --------------------
__global__ void kB() {
    const int t0 = blockIdx.x * 16;
    const int s0 = blockIdx.y * 16;
    const int bz = blockIdx.z * 8;
    const int tx = threadIdx.x & 15;
    const int ty = threadIdx.x >> 4;
    __shared__ __align__(16) float Us[16][36];
    __shared__ __align__(16) float Vs[16][36];
    float acc = 0.f;
    for (int b = bz; b < bz + 8; b++) {
        __syncthreads();
        {
            int idx = threadIdx.x;
            int r = idx >> 5, c = idx & 31;
            Us[r][c] = g_U[((size_t)b*Nn + s0 + r)*Dn + c];
            Vs[r][c] = g_V[((size_t)b*Nn + t0 + r)*Dn + c];
            idx += 256; r = idx >> 5; c = idx & 31;
            Us[r][c] = g_U[((size_t)b*Nn + s0 + r)*Dn + c];
            Vs[r][c] = g_V[((size_t)b*Nn + t0 + r)*Dn + c];
        }
        __syncthreads();
        #pragma unroll
        for (int q = 0; q < 8; q++) {
            float4 u = *(const float4*)&Us[ty][4*q];
            float4 v = *(const float4*)&Vs[tx][4*q];
            acc += u.x*v.x + u.y*v.y + u.z*v.z + u.w*v.w;
        }
    }
    atomicAdd(&g_C[(s0+ty)*Nn + (t0+tx)], acc);
}

// ---------------- Kernel C: mma.sync tf32 per (i, batch) tile ----------------
// grid = (128, 16), block = 128 (4 warps); each CTA does 4 batch tiles.
__global__ void __launch_bounds__(128, 4) kC(
        const float* __restrict__ inp,
        const float* __restrict__ W2, const float* __restrict__ b2,
        const float* __restrict__ W3, const float* __restrict__ b3,
        const float* __restrict__ Wf1, const float* __restrict__ bf1,
        const float* __restrict__ g1, const float* __restrict__ be1,
        float* __restrict__ outEdges) {
    __shared__ __align__(16) float buf[128*36];   // V stage / red (reused)
    __shared__ float W3s[1056], w3c0[32], b2s[32], b3s[36];
    __shared__ float us[4][32], xs[4][32], scs[128], shs[128];
    __shared__ float zpart[132], zsp[36], aggs[32];

    const int i   = blockIdx.x;
    const int bb  = blockIdx.y * 4;
    const int tid = threadIdx.x;
    const int warp = tid >> 5;
    const int lane = tid & 31;
    const int g = lane >> 2, c = lane & 3;
    const int wrow = warp * 32;

    // ---- one-time loads ----
    for (int idx = tid; idx < 1056; idx += 128) W3s[idx] = W3[idx];
    if (tid < 32) { w3c0[tid] = W3[tid*33]; b2s[tid] = b2[tid]; }
    if (tid < 33) b3s[tid] = b3[tid];
    {
        const int b = tid >> 5, k = tid & 31;
        us[b][k] = g_U[((size_t)(bb+b)*Nn + i)*Dn + k];
        xs[b][k] = inp[((size_t)(bb+b)*Nn + i)*Dn + k];
    }
    if (tid < 127) {
        const int t = tid + (tid >= i);
        const int p = i * Gn + tid;
        const float inv = 1.0f / 2048.0f;
        float m  = (g_sumU[i] + g_sumV[t]) * inv;
        float e2 = (g_sumU2[i] + g_sumV2[t] + 2.0f * g_C[i*Nn + t]) * inv;
        float sc = rsqrtf(e2 - m*m + EPSf) * g1[p];
        scs[tid] = sc; shs[tid] = be1[p] - m * sc;
    } else if (tid == 127) { scs[127] = 0.f; shs[127] = 0.f; }

    // ---- B fragments (W2, k x n), tf32, persistent in registers ----
    u32 bf[4][4][2];
    #pragma unroll
    for (int kk = 0; kk < 4; kk++)
        #pragma unroll
        for (int nj = 0; nj < 4; nj++) {
            bf[kk][nj][0] = tf32b(W2[(kk*8 + c)*32 + nj*8 + g]);
            bf[kk][nj][1] = tf32b(W2[(kk*8 + c + 4)*32 + nj*8 + g]);
        }
    __syncthreads();

    float fs = 0.f, fs2 = 0.f;   // per-thread f-stat accumulators (tid<16)
    const float b3s0 = b3s[0];

    for (int it = 0; it < 4; it++) {
        const int bg = bb + it;

        // ---- stage V[bg] (128x32) into buf rows padded to 36 ----
        {
            const float4* src = (const float4*)(g_V + (size_t)bg*Nn*Dn);
            #pragma unroll
            for (int m = 0; m < 8; m++) {
                int f = m*128 + tid;
                int row = f >> 3, q = f & 7;
                *(float4*)&buf[row*36 + q*4] = src[f];
            }
        }
        __syncthreads();

        // ---- fragments + mma (split by mi to bound registers) ----
        float acc[2][4][4];
        const float* ub = us[it];
        #pragma unroll
        for (int mi = 0; mi < 2; mi++) {
            const int r0 = wrow + mi*16 + g, r1 = r0 + 8;
            int t0 = r0 + (r0 >= i); if (t0 > 127) t0 = 127;
            int t1 = r1 + (r1 >= i); if (t1 > 127) t1 = 127;
            const float sc0 = scs[r0], sh0 = shs[r0];
            const float sc1 = scs[r1], sh1 = shs[r1];

            u32 af[4][4];
            #pragma unroll
            for (int kk = 0; kk < 4; kk++) {
                const int k0 = kk*8 + c, k1 = k0 + 4;
                af[kk][0] = tf32b(leaky((ub[k0] + buf[t0*36 + k0]) * sc0 + sh0));
                af[kk][1] = tf32b(leaky((ub[k0] + buf[t1*36 + k0]) * sc1 + sh1));
                af[kk][2] = tf32b(leaky((ub[k1] + buf[t0*36 + k1]) * sc0 + sh0));
                af[kk][3] = tf32b(leaky((ub[k1] + buf[t1*36 + k1]) * sc1 + sh1));
            }
            #pragma unroll
            for (int nj = 0; nj < 4; nj++) {
                acc[mi][nj][0] = 0.f; acc[mi][nj][1] = 0.f;
                acc[mi][nj][2] = 0.f; acc[mi][nj][3] = 0.f;
                #pragma unroll
                for (int kk = 0; kk < 4; kk++)
                    mma_tf32(acc[mi][nj], af[kk], bf[kk][nj]);
            }
        }
        __syncthreads();   // all V reads done -> buf reusable as red

        // ---- epilogue: bias + leaky + gate; store red = gate*a2 ----
        #pragma unroll
        for (int mi = 0; mi < 2; mi++) {
            const int r0 = wrow + mi*16 + g, r1 = r0 + 8;
            float d0 = 0.f, d1 = 0.f;
            #pragma unroll
            for (int nj = 0; nj < 4; nj++) {
                const int col0 = nj*8 + c*2;
                acc[mi][nj][0] = leaky(acc[mi][nj][0] + b2s[col0]);
                acc[mi][nj][1] = leaky(acc[mi][nj][1] + b2s[col0+1]);
                acc[mi][nj][2] = leaky(acc[mi][nj][2] + b2s[col0]);
                acc[mi][nj][3] = leaky(acc[mi][nj][3] + b2s[col0+1]);
                d0 += acc[mi][nj][0]*w3c0[col0] + acc[mi][nj][1]*w3c0[col0+1];
                d1 += acc[mi][nj][2]*w3c0[col0] + acc[mi][nj][3]*w3c0[col0+1];
            }
            d0 += __shfl_xor_sync(0xffffffffu, d0, 1);
            d0 += __shfl_xor_sync(0xffffffffu, d0, 2);
            d1 += __shfl_xor_sync(0xffffffffu, d1, 1);
            d1 += __shfl_xor_sync(0xffffffffu, d1, 2);
            float g0 = (r0 < Gn) ? 1.0f/(1.0f + __expf(-(b3s0 + d0))) : 0.f;
            float g1v = (r1 < Gn) ? 1.0f/(1.0f + __expf(-(b3s0 + d1))) : 0.f;
            if (c == 0) {
                if (r0 < Gn) outEdges[(size_t)bg*Pn + i*Gn + r0] = g0;
                if (r1 < Gn) outEdges[(size_t)bg*Pn + i*Gn + r1] = g1v;
                buf[r0*36 + 32] = g0;
                buf[r1*36 + 32] = g1v;
            }
            #pragma unroll
            for (int nj = 0; nj < 4; nj++) {
                const int col0 = nj*8 + c*2;
                buf[r0*36 + col0]   = g0  * acc[mi][nj][0];
                buf[r0*36 + col0+1] = g0  * acc[mi][nj][1];
                buf[r1*36 + col0]   = g1v * acc[mi][nj][2];
                buf[r1*36 + col0+1] = g1v * acc[mi][nj][3];
            }
        }
        __syncthreads();

        // ---- z reduction stage 1: 132 units (33 ch x 4 quarters) ----
        #pragma unroll
        for (int pass = 0; pass < 2; pass++) {
            int u = tid + pass*128;
            if (u < 132) {
                int q = u / 33, cx = u - q*33;
                float s = 0.f;
                #pragma unroll 8
                for (int r = q*32; r < q*32 + 32; r++) s += buf[r*36 + cx];
                zpart[cx*4 + q] = s;
            }
        }
        __syncthreads();
        if (tid < 33) {
            const float* zp = &zpart[tid*4];
            zsp[tid] = (zp[0] + zp[1]) + (zp[2] + zp[3]);
        }
        __syncthreads();

        // ---- agg[d] = G*b3[d+1] + sum_c z[c]*W3[c][d+1] ----
        if (tid < 32) {
            const float G = zsp[32];
            float a = G * b3s[tid + 1];
            #pragma unroll
            for (int cc = 0; cc < 32; cc++) a += zsp[cc] * W3s[cc*33 + (tid + 1)];
            aggs[tid] = a;
        }
        __syncthreads();

        // ---- f = [x, agg] @ Wf1 + bf1 ----
        if (tid < HFn) {
            const float* xb = xs[it];
            float a = bf1[tid];
            #pragma unroll
            for (int k = 0; k < 32; k++) a += xb[k] * Wf1[k*HFn + tid];
            #pragma unroll
            for (int k = 0; k < 32; k++) a += aggs[k] * Wf1[(32+k)*HFn + tid];
            g_f[((size_t)bg*Nn + i)*HFn + tid] = a;
            fs += a; fs2 += a*a;
        }
        __syncthreads();
    }

    if (tid < HFn) {
        atomicAdd(&g_fsum[tid],  fs);
        atomicAdd(&g_fsum2[tid], fs2);
    }
}

// ---------------- Kernel F: final LN (inline params) + MLP -> out -------------
__global__ void kF(const float* __restrict__ gf, const float* __restrict__ bef,
                   const float* __restrict__ Wf2, const float* __restrict__ bf2,
                   float* __restrict__ outp) {
    __shared__ __align__(16) float Wf2s[16*32];
    __shared__ float lnsc[16], lnsh[16], bf2s[32];
    const int tid = threadIdx.x;
    for (int idx = tid; idx < 16*32; idx += 128) Wf2s[idx] = Wf2[idx];
    if (tid < 16) {
        const float invR = 1.0f / 8192.0f;
        float mean = g_fsum[tid] * invR;
        float var  = g_fsum2[tid] * invR - mean * mean;
        float sc = rsqrtf(var + EPSf) * gf[tid];
        lnsc[tid] = sc;
        lnsh[tid] = bef[tid] - mean * sc;
    }
    if (tid < 32) bf2s[tid] = bf2[tid];
    __syncthreads();

    const int gt = blockIdx.x * 128 + tid;
    const int r = gt >> 1;
    const int half = (gt & 1) * 16;

    float gq[16];
    #pragma unroll
    for (int j = 0; j < 16; j++) {
        float v = g_f[(size_t)r*HFn + j];
        gq[j] = leaky(v * lnsc[j] + lnsh[j]);
    }
    float4* op = (float4*)(outp + (size_t)r * Dn + half);
    #pragma unroll
    for (int q = 0; q < 4; q++) {
        float o[4];
        #pragma unroll
        for (int u = 0; u < 4; u++) {
            int cc = half + 4*q + u;
            float a = bf2s[cc];
            #pragma unroll
            for (int j = 0; j < 16; j++) a += gq[j] * Wf2s[j*32 + cc];
            o[u] = a;
        }
        op[q] = make_float4(o[0], o[1], o[2], o[3]);
    }
}

// ---------------- launch ------------------------------------------------------
extern "C" void kernel_launch(void* const* d_in, const int* in_sizes, int n_in,
                              void* d_out, int out_size) {
    const float* inp = (const float*)d_in[0];
    const float* W1  = (const float*)d_in[3];
    const float* b1  = (const float*)d_in[4];
    const float* g1  = (const float*)d_in[5];
    const float* be1 = (const float*)d_in[6];
    const float* W2  = (const float*)d_in[7];
    const float* b2  = (const float*)d_in[8];
    const float* W3  = (const float*)d_in[9];
    const float* b3  = (const float*)d_in[10];
    const float* Wf1 = (const float*)d_in[11];
    const float* bf1 = (const float*)d_in[12];
    const float* gf  = (const float*)d_in[13];
    const float* bef = (const float*)d_in[14];
    const float* Wf2 = (const float*)d_in[15];
    const float* bf2 = (const float*)d_in[16];

    float* outEdges = (float*)d_out;
    float* outFeat  = (float*)d_out + (size_t)Bn * Pn;

    kA<<<Nn, 64>>>(inp, W1, b1);
    kB<<<dim3(8, 8, 8), 256>>>();
    kC<<<dim3(Nn, Bn/4), 128>>>(inp, W2, b2, W3, b3, Wf1, bf1, g1, be1, outEdges);
    kF<<<128, 128>>>(gf, bef, Wf2, bf2, outFeat);
}

// round 13
// speedup vs baseline: 1.8996x; 1.2050x over previous
#include <cuda_runtime.h>
#include <math.h>

#define Bn 64
#define Nn 128
#define Dn 32
#define Gn 127              // N-1
#define Pn (Nn*(Nn-1))      // 16256
#define HFn 16
#define EPSf 1e-5f

typedef unsigned int u32;

// ---------------- scratch (static device globals; no allocation) -------------
__device__ float g_U[Bn*Nn*Dn];
__device__ float g_V[Bn*Nn*Dn];
__device__ float g_sumU[Nn], g_sumU2[Nn], g_sumV[Nn], g_sumV2[Nn];
__device__ float g_C[Nn*Nn];
__device__ float g_f[Bn*Nn*HFn];
__device__ float g_fsum[HFn], g_fsum2[HFn];

__device__ __forceinline__ float leaky(float x) { return x > 0.f ? x : 0.01f * x; }

__device__ __forceinline__ u32 tf32b(float x) {
    u32 y; asm("cvt.rna.tf32.f32 %0, %1;" : "=r"(y) : "f"(x));
    return y;
}
__device__ __forceinline__ void mma_tf32(float* d, const u32* a, const u32* b) {
    asm volatile(
        "mma.sync.aligned.m16n8k8.row.col.f32.tf32.tf32.f32 "
        "{%0,%1,%2,%3}, {%4,%5,%6,%7}, {%8,%9}, {%0,%1,%2,%3};"
        : "+f"(d[0]), "+f"(d[1]), "+f"(d[2]), "+f"(d[3])
        : "r"(a[0]), "r"(a[1]), "r"(a[2]), "r"(a[3]), "r"(b[0]), "r"(b[1]));
}

// ---------------- Kernel A: per-node projections + stats + zeroing -----------
__global__ void kA(const float* __restrict__ inp, const float* __restrict__ W1,
                   const float* __restrict__ b1) {
    const int n = blockIdx.x;
    const int b = threadIdx.x;
    __shared__ __align__(16) float W1t[32*64];
    __shared__ float red[64*4];

    g_C[n*128 + b*2]     = 0.f;
    g_C[n*128 + b*2 + 1] = 0.f;
    if (n == 0 && b < HFn) { g_fsum[b] = 0.f; g_fsum2[b] = 0.f; }

    for (int idx = b; idx < 2048; idx += 64) {
        int k = idx & 63, c = idx >> 6;
        W1t[c*64 + k] = W1[k*32 + c];
    }
    __syncthreads();

    float x[32];
    const float4* xp = (const float4*)(inp + ((size_t)b*Nn + n)*Dn);
    #pragma unroll
    for (int q = 0; q < 8; q++) {
        float4 v = xp[q];
        x[4*q+0]=v.x; x[4*q+1]=v.y; x[4*q+2]=v.z; x[4*q+3]=v.w;
    }
    float su=0.f, su2=0.f, sv=0.f, sv2=0.f;
    float* Uo = g_U + ((size_t)b*Nn + n)*Dn;
    float* Vo = g_V + ((size_t)b*Nn + n)*Dn;
    #pragma unroll 4
    for (int c = 0; c < 32; c++) {
        const float4* wr = (const float4*)(W1t + c*64);
        float u = b1[c], v = 0.f;
        #pragma unroll
        for (int j = 0; j < 8; j++) {
            float4 wu = wr[j], wv = wr[8 + j];
            u += x[4*j+0]*wu.x + x[4*j+1]*wu.y + x[4*j+2]*wu.z + x[4*j+3]*wu.w;
            v += x[4*j+0]*wv.x + x[4*j+1]*wv.y + x[4*j+2]*wv.z + x[4*j+3]*wv.w;
        }
        Uo[c] = u; Vo[c] = v;
        su += u; su2 += u*u; sv += v; sv2 += v*v;
    }
    red[b] = su; red[64+b] = su2; red[128+b] = sv; red[192+b] = sv2;
    __syncthreads();
    for (int s = 32; s > 0; s >>= 1) {
        if (b < s) {
            red[b] += red[b+s]; red[64+b] += red[64+b+s];
            red[128+b] += red[128+b+s]; red[192+b] += red[192+b+s];
        }
        __syncthreads();
    }
    if (b == 0) {
        g_sumU[n] = red[0]; g_sumU2[n] = red[64];
        g_sumV[n] = red[128]; g_sumV2[n] = red[192];
    }
}

// ---------------- Kernel B: cross term C[s,t], K-split x8 --------------------
__global__ void kB() {
    const int t0 = blockIdx.x * 16;
    const int s0 = blockIdx.y * 16;
    const int bz = blockIdx.z * 8;
    const int tx = threadIdx.x & 15;
    const int ty = threadIdx.x >> 4;
    __shared__ __align__(16) float Us[16][36];
    __shared__ __align__(16) float Vs[16][36];
    float acc = 0.f;
    for (int b = bz; b < bz + 8; b++) {
        __syncthreads();
        {
            int idx = threadIdx.x;
            int r = idx >> 5, c = idx & 31;
            Us[r][c] = g_U[((size_t)b*Nn + s0 + r)*Dn + c];
            Vs[r][c] = g_V[((size_t)b*Nn + t0 + r)*Dn + c];
            idx += 256; r = idx >> 5; c = idx & 31;
            Us[r][c] = g_U[((size_t)b*Nn + s0 + r)*Dn + c];
            Vs[r][c] = g_V[((size_t)b*Nn + t0 + r)*Dn + c];
        }
        __syncthreads();
        #pragma unroll
        for (int q = 0; q < 8; q++) {
            float4 u = *(const float4*)&Us[ty][4*q];
            float4 v = *(const float4*)&Vs[tx][4*q];
            acc += u.x*v.x + u.y*v.y + u.z*v.z + u.w*v.w;
        }
    }
    atomicAdd(&g_C[(s0+ty)*Nn + (t0+tx)], acc);
}

// ---------------- Kernel C: mma.sync tf32, shuffle-reduced epilogue ----------
// grid = (128, 16), block = 128 (4 warps); each CTA does 4 batch tiles.
__global__ void __launch_bounds__(128, 4) kC(
        const float* __restrict__ inp,
        const float* __restrict__ W2, const float* __restrict__ b2,
        const float* __restrict__ W3, const float* __restrict__ b3,
        const float* __restrict__ Wf1, const float* __restrict__ bf1,
        const float* __restrict__ g1, const float* __restrict__ be1,
        float* __restrict__ outEdges) {
    __shared__ __align__(16) float buf[128*36];   // V staging only
    __shared__ float W3s[1056], w3c0[32], b2s[32], b3s[36];
    __shared__ float us[4][32], xs[4][32], scs[128], shs[128];
    __shared__ float zw[4][36];                   // per-warp col sums + G
    __shared__ float aggs[32];

    const int i   = blockIdx.x;
    const int bb  = blockIdx.y * 4;
    const int tid = threadIdx.x;
    const int warp = tid >> 5;
    const int lane = tid & 31;
    const int g = lane >> 2, c = lane & 3;
    const int wrow = warp * 32;

    // ---- one-time loads ----
    for (int idx = tid; idx < 1056; idx += 128) W3s[idx] = W3[idx];
    if (tid < 32) { w3c0[tid] = W3[tid*33]; b2s[tid] = b2[tid]; }
    if (tid < 33) b3s[tid] = b3[tid];
    {
        const int b = tid >> 5, k = tid & 31;
        us[b][k] = g_U[((size_t)(bb+b)*Nn + i)*Dn + k];
        xs[b][k] = inp[((size_t)(bb+b)*Nn + i)*Dn + k];
    }
    if (tid < 127) {
        const int t = tid + (tid >= i);
        const int p = i * Gn + tid;
        const float inv = 1.0f / 2048.0f;
        float m  = (g_sumU[i] + g_sumV[t]) * inv;
        float e2 = (g_sumU2[i] + g_sumV2[t] + 2.0f * g_C[i*Nn + t]) * inv;
        float sc = rsqrtf(e2 - m*m + EPSf) * g1[p];
        scs[tid] = sc; shs[tid] = be1[p] - m * sc;
    } else if (tid == 127) { scs[127] = 0.f; shs[127] = 0.f; }

    // ---- B fragments (W2, k x n), tf32, persistent in registers ----
    u32 bf[4][4][2];
    #pragma unroll
    for (int kk = 0; kk < 4; kk++)
        #pragma unroll
        for (int nj = 0; nj < 4; nj++) {
            bf[kk][nj][0] = tf32b(W2[(kk*8 + c)*32 + nj*8 + g]);
            bf[kk][nj][1] = tf32b(W2[(kk*8 + c + 4)*32 + nj*8 + g]);
        }

    // ---- stage V for tile 0 ----
    {
        const float4* src = (const float4*)(g_V + (size_t)bb*Nn*Dn);
        #pragma unroll
        for (int m = 0; m < 8; m++) {
            int f = m*128 + tid;
            int row = f >> 3, q = f & 7;
            *(float4*)&buf[row*36 + q*4] = src[f];
        }
    }
    __syncthreads();

    float fs = 0.f, fs2 = 0.f;
    const float b3s0 = b3s[0];

    for (int it = 0; it < 4; it++) {
        const int bg = bb + it;

        // ---- fragments + mma ----
        float acc[2][4][4];
        const float* ub = us[it];
        #pragma unroll
        for (int mi = 0; mi < 2; mi++) {
            const int r0 = wrow + mi*16 + g, r1 = r0 + 8;
            int t0 = r0 + (r0 >= i); if (t0 > 127) t0 = 127;
            int t1 = r1 + (r1 >= i); if (t1 > 127) t1 = 127;
            const float sc0 = scs[r0], sh0 = shs[r0];
            const float sc1 = scs[r1], sh1 = shs[r1];

            u32 af[4][4];
            #pragma unroll
            for (int kk = 0; kk < 4; kk++) {
                const int k0 = kk*8 + c, k1 = k0 + 4;
                af[kk][0] = tf32b(leaky((ub[k0] + buf[t0*36 + k0]) * sc0 + sh0));
                af[kk][1] = tf32b(leaky((ub[k0] + buf[t1*36 + k0]) * sc1 + sh1));
                af[kk][2] = tf32b(leaky((ub[k1] + buf[t0*36 + k1]) * sc0 + sh0));
                af[kk][3] = tf32b(leaky((ub[k1] + buf[t1*36 + k1]) * sc1 + sh1));
            }
            #pragma unroll
            for (int nj = 0; nj < 4; nj++) {
                acc[mi][nj][0] = 0.f; acc[mi][nj][1] = 0.f;
                acc[mi][nj][2] = 0.f; acc[mi][nj][3] = 0.f;
                #pragma unroll
                for (int kk = 0; kk < 4; kk++)
                    mma_tf32(acc[mi][nj], af[kk], bf[kk][nj]);
            }
        }

        // ---- epilogue: bias + leaky + gate; z in registers ----
        float zp[8];
        #pragma unroll
        for (int j = 0; j < 8; j++) zp[j] = 0.f;
        float gsum = 0.f;

        #pragma unroll
        for (int mi = 0; mi < 2; mi++) {
            const int r0 = wrow + mi*16 + g, r1 = r0 + 8;
            float d0 = 0.f, d1 = 0.f;
            #pragma unroll
            for (int nj = 0; nj < 4; nj++) {
                const int col0 = nj*8 + c*2;
                acc[mi][nj][0] = leaky(acc[mi][nj][0] + b2s[col0]);
                acc[mi][nj][1] = leaky(acc[mi][nj][1] + b2s[col0+1]);
                acc[mi][nj][2] = leaky(acc[mi][nj][2] + b2s[col0]);
                acc[mi][nj][3] = leaky(acc[mi][nj][3] + b2s[col0+1]);
                d0 += acc[mi][nj][0]*w3c0[col0] + acc[mi][nj][1]*w3c0[col0+1];
                d1 += acc[mi][nj][2]*w3c0[col0] + acc[mi][nj][3]*w3c0[col0+1];
            }
            d0 += __shfl_xor_sync(0xffffffffu, d0, 1);
            d0 += __shfl_xor_sync(0xffffffffu, d0, 2);
            d1 += __shfl_xor_sync(0xffffffffu, d1, 1);
            d1 += __shfl_xor_sync(0xffffffffu, d1, 2);
            float g0  = (r0 < Gn) ? 1.0f/(1.0f + __expf(-(b3s0 + d0))) : 0.f;
            float g1v = (r1 < Gn) ? 1.0f/(1.0f + __expf(-(b3s0 + d1))) : 0.f;
            if (c == 0) {
                if (r0 < Gn) outEdges[(size_t)bg*Pn + i*Gn + r0] = g0;
                if (r1 < Gn) outEdges[(size_t)bg*Pn + i*Gn + r1] = g1v;
            }
            gsum += g0 + g1v;
            #pragma unroll
            for (int nj = 0; nj < 4; nj++) {
                zp[nj*2+0] += g0*acc[mi][nj][0] + g1v*acc[mi][nj][2];
                zp[nj*2+1] += g0*acc[mi][nj][1] + g1v*acc[mi][nj][3];
            }
        }

        // reduce over row-groups g (lanes differing in bits 2,3,4)
        #pragma unroll
        for (int s = 4; s <= 16; s <<= 1) {
            #pragma unroll
            for (int j = 0; j < 8; j++)
                zp[j] += __shfl_xor_sync(0xffffffffu, zp[j], s);
            gsum += __shfl_xor_sync(0xffffffffu, gsum, s);
        }
        if (lane < 4) {   // lane == c, g == 0: holds warp sums for its 8 cols
            #pragma unroll
            for (int nj = 0; nj < 4; nj++) {
                zw[warp][nj*8 + lane*2 + 0] = zp[nj*2+0];
                zw[warp][nj*8 + lane*2 + 1] = zp[nj*2+1];
            }
        }
        if (lane == 0) zw[warp][32] = gsum;
        __syncthreads();

        // ---- agg (tid<32) overlapped with staging next V tile ----
        if (tid < 32) {
            const float G = zw[0][32] + zw[1][32] + zw[2][32] + zw[3][32];
            float a = G * b3s[tid + 1];
            #pragma unroll
            for (int cc = 0; cc < 32; cc++) {
                float z = zw[0][cc] + zw[1][cc] + zw[2][cc] + zw[3][cc];
                a += z * W3s[cc*33 + (tid + 1)];
            }
            aggs[tid] = a;
        } else if (it < 3) {
            // stage next V with threads 32..127 (3/4 of the loads)
            const float4* src = (const float4*)(g_V + (size_t)(bg+1)*Nn*Dn);
            #pragma unroll
            for (int m = 0; m < 8; m++) {
                int f = m*96 + (tid - 32);
                if (f < 1024) {
                    int row = f >> 3, q = f & 7;
                    *(float4*)&buf[row*36 + q*4] = src[f];
                }
            }
        }
        __syncthreads();

        // remaining quarter of next V staging by all threads
        if (it < 3) {
            const float4* src = (const float4*)(g_V + (size_t)(bg+1)*Nn*Dn);
            int f = 768 + tid;   // 768..895
            {
                int row = f >> 3, q = f & 7;
                *(float4*)&buf[row*36 + q*4] = src[f];
            }
            f = 896 + tid;
            if (f < 1024) {
                int row = f >> 3, q = f & 7;
                *(float4*)&buf[row*36 + q*4] = src[f];
            }
        }

        // ---- f = [x, agg] @ Wf1 + bf1 ----
        if (tid < HFn) {
            const float* xb = xs[it];
            float a = bf1[tid];
            #pragma unroll
            for (int k = 0; k < 32; k++) a += xb[k] * Wf1[k*HFn + tid];
            #pragma unroll
            for (int k = 0; k < 32; k++) a += aggs[k] * Wf1[(32+k)*HFn + tid];
            g_f[((size_t)bg*Nn + i)*HFn + tid] = a;
            fs += a; fs2 += a*a;
        }
        __syncthreads();
    }

    if (tid < HFn) {
        atomicAdd(&g_fsum[tid],  fs);
        atomicAdd(&g_fsum2[tid], fs2);
    }
}

// ---------------- Kernel F: final LN (inline params) + MLP -> out -------------
__global__ void kF(const float* __restrict__ gf, const float* __restrict__ bef,
                   const float* __restrict__ Wf2, const float* __restrict__ bf2,
                   float* __restrict__ outp) {
    __shared__ __align__(16) float Wf2s[16*32];
    __shared__ float lnsc[16], lnsh[16], bf2s[32];
    const int tid = threadIdx.x;
    for (int idx = tid; idx < 16*32; idx += 128) Wf2s[idx] = Wf2[idx];
    if (tid < 16) {
        const float invR = 1.0f / 8192.0f;
        float mean = g_fsum[tid] * invR;
        float var  = g_fsum2[tid] * invR - mean * mean;
        float sc = rsqrtf(var + EPSf) * gf[tid];
        lnsc[tid] = sc;
        lnsh[tid] = bef[tid] - mean * sc;
    }
    if (tid < 32) bf2s[tid] = bf2[tid];
    __syncthreads();

    const int gt = blockIdx.x * 128 + tid;
    const int r = gt >> 1;
    const int half = (gt & 1) * 16;

    float gq[16];
    #pragma unroll
    for (int j = 0; j < 16; j++) {
        float v = g_f[(size_t)r*HFn + j];
        gq[j] = leaky(v * lnsc[j] + lnsh[j]);
    }
    float4* op = (float4*)(outp + (size_t)r * Dn + half);
    #pragma unroll
    for (int q = 0; q < 4; q++) {
        float o[4];
        #pragma unroll
        for (int u = 0; u < 4; u++) {
            int cc = half + 4*q + u;
            float a = bf2s[cc];
            #pragma unroll
            for (int j = 0; j < 16; j++) a += gq[j] * Wf2s[j*32 + cc];
            o[u] = a;
        }
        op[q] = make_float4(o[0], o[1], o[2], o[3]);
    }
}

// ---------------- launch ------------------------------------------------------
extern "C" void kernel_launch(void* const* d_in, const int* in_sizes, int n_in,
                              void* d_out, int out_size) {
    const float* inp = (const float*)d_in[0];
    const float* W1  = (const float*)d_in[3];
    const float* b1  = (const float*)d_in[4];
    const float* g1  = (const float*)d_in[5];
    const float* be1 = (const float*)d_in[6];
    const float* W2  = (const float*)d_in[7];
    const float* b2  = (const float*)d_in[8];
    const float* W3  = (const float*)d_in[9];
    const float* b3  = (const float*)d_in[10];
    const float* Wf1 = (const float*)d_in[11];
    const float* bf1 = (const float*)d_in[12];
    const float* gf  = (const float*)d_in[13];
    const float* bef = (const float*)d_in[14];
    const float* Wf2 = (const float*)d_in[15];
    const float* bf2 = (const float*)d_in[16];

    float* outEdges = (float*)d_out;
    float* outFeat  = (float*)d_out + (size_t)Bn * Pn;

    kA<<<Nn, 64>>>(inp, W1, b1);
    kB<<<dim3(8, 8, 8), 256>>>();
    kC<<<dim3(Nn, Bn/4), 128>>>(inp, W2, b2, W3, b3, Wf1, bf1, g1, be1, outEdges);
    kF<<<128, 128>>>(gf, bef, Wf2, bf2, outFeat);
}